// round 1
// baseline (speedup 1.0000x reference)
#include <cuda_runtime.h>

#define NN 50000
#define NE 800000
#define F  128

// Scratch (device globals: no allocations allowed)
__device__ float g_deg_out[NN];
__device__ float g_deg_in[NN];
__device__ float g_xn[NN * F];
__device__ float g_h[NN * F];

// ---------------------------------------------------------------------------
// 1) Zero scratch: h (6.4M floats) + both degree arrays
// ---------------------------------------------------------------------------
__global__ void zero_kernel() {
    int i = blockIdx.x * blockDim.x + threadIdx.x;
    int n4 = NN * F / 4;
    if (i < n4) reinterpret_cast<float4*>(g_h)[i] = make_float4(0.f, 0.f, 0.f, 0.f);
    if (i < NN) { g_deg_out[i] = 0.f; g_deg_in[i] = 0.f; }
}

// ---------------------------------------------------------------------------
// 2) Degree accumulation (scalar float atomics; 1.6M ops, cheap)
// ---------------------------------------------------------------------------
__global__ void deg_kernel(const int* __restrict__ src, const int* __restrict__ dst) {
    int e = blockIdx.x * blockDim.x + threadIdx.x;
    if (e < NE) {
        atomicAdd(&g_deg_out[src[e]], 1.0f);
        atomicAdd(&g_deg_in[dst[e]], 1.0f);
    }
}

// ---------------------------------------------------------------------------
// 3) Left normalization: xn = x * rsqrt(max(deg_out, 1))
// ---------------------------------------------------------------------------
__global__ void scale_kernel(const float* __restrict__ x) {
    int i = blockIdx.x * blockDim.x + threadIdx.x;   // over NN * 32 float4s
    if (i < NN * (F / 4)) {
        int node = i / (F / 4);
        float inv = rsqrtf(fmaxf(g_deg_out[node], 1.0f));
        float4 v = reinterpret_cast<const float4*>(x)[i];
        v.x *= inv; v.y *= inv; v.z *= inv; v.w *= inv;
        reinterpret_cast<float4*>(g_xn)[i] = v;
    }
}

// ---------------------------------------------------------------------------
// 4) Edge aggregation: h[dst] += xn[src]   (one warp per edge, v4 red atomics)
// ---------------------------------------------------------------------------
__global__ void agg_kernel(const int* __restrict__ src, const int* __restrict__ dst) {
    int gtid = blockIdx.x * blockDim.x + threadIdx.x;
    int e    = gtid >> 5;
    int lane = threadIdx.x & 31;
    if (e < NE) {
        int s = src[e];
        int d = dst[e];
        float4 v = reinterpret_cast<const float4*>(g_xn + (size_t)s * F)[lane];
        float* hp = g_h + (size_t)d * F + lane * 4;
        asm volatile("red.global.add.v4.f32 [%0], {%1, %2, %3, %4};"
                     :: "l"(hp), "f"(v.x), "f"(v.y), "f"(v.z), "f"(v.w)
                     : "memory");
    }
}

// ---------------------------------------------------------------------------
// 5) GEMM (h @ W) fused with right norm + bias
//    Block: 256 threads, 32 rows/block. W (64KB) + H tile (16KB) in smem.
//    Warp w handles rows [4w..4w+3]; lane handles cols [4*lane..4*lane+3].
// ---------------------------------------------------------------------------
__global__ void __launch_bounds__(256, 2)
gemm_kernel(const float* __restrict__ weight, const float* __restrict__ bias,
            float* __restrict__ out) {
    extern __shared__ float sm[];
    float* Wsh = sm;            // 128*128
    float* Hsh = sm + F * F;    // 32*128

    int tid  = threadIdx.x;
    int row0 = blockIdx.x * 32;

    // Load W (coalesced float4)
    for (int i = tid; i < F * F / 4; i += 256)
        reinterpret_cast<float4*>(Wsh)[i] = reinterpret_cast<const float4*>(weight)[i];
    // Load H tile (guard tail block)
    for (int i = tid; i < 32 * F / 4; i += 256) {
        int gidx = row0 * (F / 4) + i;
        float4 v = make_float4(0.f, 0.f, 0.f, 0.f);
        if (gidx < NN * (F / 4))
            v = reinterpret_cast<const float4*>(g_h)[gidx];
        reinterpret_cast<float4*>(Hsh)[i] = v;
    }
    __syncthreads();

    int warp = tid >> 5;
    int lane = tid & 31;
    int r0 = warp * 4;

    float4 acc[4];
#pragma unroll
    for (int r = 0; r < 4; r++) acc[r] = make_float4(0.f, 0.f, 0.f, 0.f);

#pragma unroll 4
    for (int k = 0; k < F; k++) {
        float4 wv = reinterpret_cast<float4*>(Wsh)[k * 32 + lane];  // conflict-free
#pragma unroll
        for (int r = 0; r < 4; r++) {
            float hv = Hsh[(r0 + r) * F + k];                        // warp broadcast
            acc[r].x += hv * wv.x;
            acc[r].y += hv * wv.y;
            acc[r].z += hv * wv.z;
            acc[r].w += hv * wv.w;
        }
    }

    float4 bv = reinterpret_cast<const float4*>(bias)[lane];
#pragma unroll
    for (int r = 0; r < 4; r++) {
        int row = row0 + r0 + r;
        if (row < NN) {
            float inv = rsqrtf(fmaxf(g_deg_in[row], 1.0f));
            float4 o;
            o.x = acc[r].x * inv + bv.x;
            o.y = acc[r].y * inv + bv.y;
            o.z = acc[r].z * inv + bv.z;
            o.w = acc[r].w * inv + bv.w;
            reinterpret_cast<float4*>(out + (size_t)row * F)[lane] = o;
        }
    }
}

// ---------------------------------------------------------------------------
extern "C" void kernel_launch(void* const* d_in, const int* in_sizes, int n_in,
                              void* d_out, int out_size) {
    const float* x      = (const float*)d_in[0];
    const int*   src    = (const int*)d_in[1];
    const int*   dst    = (const int*)d_in[2];
    const float* weight = (const float*)d_in[3];
    const float* bias   = (const float*)d_in[4];
    float*       out    = (float*)d_out;

    // 1) zero scratch
    {
        int n = NN * F / 4;   // 1.6M (covers NN too)
        zero_kernel<<<(n + 255) / 256, 256>>>();
    }
    // 2) degrees
    deg_kernel<<<(NE + 255) / 256, 256>>>(src, dst);
    // 3) left norm
    {
        int n = NN * (F / 4);
        scale_kernel<<<(n + 255) / 256, 256>>>(x);
    }
    // 4) aggregation
    {
        long long threads = (long long)NE * 32;
        int blocks = (int)((threads + 255) / 256);
        agg_kernel<<<blocks, 256>>>(src, dst);
    }
    // 5) GEMM + right norm + bias
    {
        int smem = (F * F + 32 * F) * (int)sizeof(float);  // 81920 B
        cudaFuncSetAttribute(gemm_kernel, cudaFuncAttributeMaxDynamicSharedMemorySize, smem);
        int blocks = (NN + 31) / 32;  // 1563
        gemm_kernel<<<blocks, 256, smem>>>(weight, bias, out);
    }
}